// round 1
// baseline (speedup 1.0000x reference)
#include <cuda_runtime.h>
#include <cuda_bf16.h>
#include <math.h>

#define BIGF 1000000000.0f

// Scratch: cost matrix in anti-diagonal layout Cdiag[b][k][i], k = i+j in [0,2046],
// padded to 2048 diagonals. 32 * 2048 * 1024 floats = 256 MB.
static __device__ float g_Cdiag[67108864];
static __device__ float g_n1[32 * 1024];
static __device__ float g_n2[32 * 1024];

// ---------------------------------------------------------------------------
// Kernel 0: row squared norms. grid (32, 2), 256 threads. Warp per row.
// ---------------------------------------------------------------------------
__global__ __launch_bounds__(256) void norms_kernel(const float* __restrict__ s1,
                                                    const float* __restrict__ s2) {
    int b = blockIdx.x;
    const float* s = blockIdx.y ? s2 : s1;
    float* o = blockIdx.y ? g_n2 : g_n1;
    int lane = threadIdx.x & 31;
    int wid = threadIdx.x >> 5;  // 8 warps
    for (int r = wid; r < 1024; r += 8) {
        const float4* p = (const float4*)(s + ((size_t)b * 1024 + r) * 128);
        float4 v = p[lane];  // 128 floats = 32 float4 per row, one per lane
        float acc = v.x * v.x + v.y * v.y + v.z * v.z + v.w * v.w;
#pragma unroll
        for (int off = 16; off; off >>= 1)
            acc += __shfl_xor_sync(0xffffffffu, acc, off);
        if (lane == 0) o[b * 1024 + r] = acc;
    }
}

// ---------------------------------------------------------------------------
// Kernel 1: cost matrix. grid (16, 16, 32) = (j-tile, i-tile, batch).
// 256 threads = 16x16, each computes a 4x4 register tile over K=128 (4 chunks of 32).
// Epilogue: C = sqrt(max(n1 + n2 - 2*dot, 0)), staged through shared memory and
// written out in anti-diagonal-major layout (coalesced diagonal segments).
// ---------------------------------------------------------------------------
__global__ __launch_bounds__(256) void cost_kernel(const float* __restrict__ s1,
                                                   const float* __restrict__ s2) {
    __shared__ float smem[4352];        // asT[32][68] + bsT[32][68]; reused as Ss[64][66]
    float* asT = smem;                  // transposed A chunk: asT[k][i], pitch 68
    float* bsT = smem + 32 * 68;        // transposed B chunk: bsT[k][j], pitch 68

    int b = blockIdx.z;
    int i0 = blockIdx.y * 64;
    int j0 = blockIdx.x * 64;
    int tid = threadIdx.x;
    int tx = tid & 15;
    int ty = tid >> 4;

    const float* A = s1 + ((size_t)b * 1024 + i0) * 128;
    const float* B = s2 + ((size_t)b * 1024 + j0) * 128;

    float acc[4][4];
#pragma unroll
    for (int u = 0; u < 4; u++)
#pragma unroll
        for (int v = 0; v < 4; v++) acc[u][v] = 0.0f;

    for (int kc0 = 0; kc0 < 128; kc0 += 32) {
        __syncthreads();
#pragma unroll
        for (int it = 0; it < 8; it++) {
            int e = tid + it * 256;      // 2048 elements = 64 rows x 32 cols
            int r = e >> 5;
            int c = e & 31;
            asT[c * 68 + r] = A[r * 128 + kc0 + c];
            bsT[c * 68 + r] = B[r * 128 + kc0 + c];
        }
        __syncthreads();
#pragma unroll
        for (int k = 0; k < 32; k++) {
            float4 a4 = *(const float4*)&asT[k * 68 + ty * 4];
            float4 b4 = *(const float4*)&bsT[k * 68 + tx * 4];
            float av[4] = {a4.x, a4.y, a4.z, a4.w};
            float bv[4] = {b4.x, b4.y, b4.z, b4.w};
#pragma unroll
            for (int u = 0; u < 4; u++)
#pragma unroll
                for (int v = 0; v < 4; v++) acc[u][v] += av[u] * bv[v];
        }
    }
    __syncthreads();

    // Epilogue: distances into staging buffer Ss[64][66] (pitch 66 makes the
    // diagonal read stride 65 -> conflict-free).
    float* Ss = smem;
#pragma unroll
    for (int u = 0; u < 4; u++) {
        float n1 = g_n1[b * 1024 + i0 + ty * 4 + u];
#pragma unroll
        for (int v = 0; v < 4; v++) {
            float n2 = g_n2[b * 1024 + j0 + tx * 4 + v];
            float d2 = n1 + n2 - 2.0f * acc[u][v];
            Ss[(ty * 4 + u) * 66 + tx * 4 + v] = sqrtf(fmaxf(d2, 0.0f));
        }
    }
    __syncthreads();

    // Diagonal write-out: 127 local diagonals d = li + lj, global k = i0 + j0 + d.
    int lane = tid & 31;
    int w8 = tid >> 5;  // 8 warps
    for (int d = w8; d < 127; d += 8) {
        int lo = d > 63 ? d - 63 : 0;
        int hi = d < 63 ? d : 63;
        size_t base = ((size_t)b * 2048 + (size_t)(i0 + j0 + d)) * 1024 + i0;
        int li = lo + lane;
        if (li <= hi) g_Cdiag[base + li] = Ss[li * 66 + (d - li)];
        li += 32;
        if (li <= hi) g_Cdiag[base + li] = Ss[li * 66 + (d - li)];
    }
}

// ---------------------------------------------------------------------------
// Kernel 2: DTW wavefront. One CTA of 1024 threads per batch.
// Thread t owns DP row i = t+1. Per anti-diagonal k (2..2048):
//   cur = C[i-1][j-1] + min(D[i][j-1], min(D[i-1][j-1], D[i-1][j]))
// where the neighbor min comes from thread t-1 via shuffle (warp-internal) or a
// double-buffered shared edge slot (warp boundary). 6-deep register ring
// prefetches cost diagonals (coalesced: Cdiag[k] is contiguous in i).
// ---------------------------------------------------------------------------
__global__ __launch_bounds__(1024) void dtw_kernel(float* __restrict__ out) {
    int b = blockIdx.x;
    int t = threadIdx.x;
    int lane = t & 31;
    int w = t >> 5;
    __shared__ float edge[2][33];

    const float* Cb = g_Cdiag + (size_t)b * 2048 * 1024;

    float prev = BIGF;   // D[i][k-1-i]
    float prev2 = BIGF;  // D[i][k-2-i]

    float cbuf[6];
#pragma unroll
    for (int q = 0; q < 6; q++) cbuf[q] = Cb[q * 1024 + t];

#pragma unroll 6
    for (int k = 2; k <= 2048; ++k) {
        int kc = k - 2;
        float cval = cbuf[kc % 6];
        int pf = kc + 6;
        if (pf > 2047) pf = 2047;
        cbuf[kc % 6] = Cb[(size_t)pf * 1024 + t];

        float nm = fminf(prev, prev2);               // min(D[i][j], D[i][j-1]) on prior diags
        if (lane == 31) edge[k & 1][w] = nm;
        __syncthreads();
        float up = __shfl_up_sync(0xffffffffu, nm, 1);  // from row i-1
        if (lane == 0) up = (w == 0) ? ((k == 2) ? 0.0f : BIGF) : edge[k & 1][w - 1];

        int j = k - t - 1;
        float cur = (j >= 1 && j <= 1024) ? (cval + fminf(prev, up)) : BIGF;
        prev2 = prev;
        prev = cur;
    }

    if (t == 1023) {
        // prev = D[1024][1024]; w[0] = softmax(single elem) == 1 exactly.
        float dist = prev * (1.0f / 2048.0f);
        out[b] = 1.0f / (1.0f + dist);
    }
}

// ---------------------------------------------------------------------------
extern "C" void kernel_launch(void* const* d_in, const int* in_sizes, int n_in,
                              void* d_out, int out_size) {
    const float* seq1 = (const float*)d_in[0];
    const float* seq2 = (const float*)d_in[1];
    // d_in[2] = scale_weights (1 elem): softmax of a single weight is exactly 1.0.
    float* out = (float*)d_out;

    dim3 gN(32, 2);
    norms_kernel<<<gN, 256>>>(seq1, seq2);

    dim3 gC(16, 16, 32);
    cost_kernel<<<gC, 256>>>(seq1, seq2);

    dtw_kernel<<<32, 1024>>>(out);
}